// round 13
// baseline (speedup 1.0000x reference)
#include <cuda_runtime.h>

#define HALFW 6
#define MAXC  63
#define NK    21
#define NB    64
#define NC    256
#define NH    64
#define NW    64
#define HW    (NH * NW)
#define NTILE 512                 // (4 strips) x 64 b x 2 tensors
#define NBLKP 444                 // 3 x 148 SMs: one perfectly even wave
#define FULLM 0xffffffffu

// Scratch (allocation-free rule: __device__ globals; zero-initialized)
__device__ float g_part[2][NK][4][NB];  // [t][k][xb][b], coalesced finisher
__device__ int   g_ticket = 0;          // work ticket (self-resetting)
__device__ int   g_done   = 0;          // blocks-exited counter (self-resetting)

// ---------------------------------------------------------------------------
// Persistent fused kernel. grid = 444 blocks (3/SM exactly), block = 256.
// Blocks draw tiles (proven R12 body) via atomic tickets: even SM load during
// the main wave, earliest finishers absorb the 68-tile remainder.
// Finisher (all blocks exited) reduces g_part + MSE + resets counters.
// ---------------------------------------------------------------------------
__global__ void __launch_bounds__(256) fused_kernel(
    const float* __restrict__ f1, const float* __restrict__ f2,
    const int* __restrict__ pre1, const int* __restrict__ pre2,
    float* __restrict__ out)
{
    const int tid  = threadIdx.x;
    const int warp = tid >> 5;
    const int lane = tid & 31;

    __shared__ __align__(16) float s_fm[16 * NW];  // fm tile (chan-mean), 4KB
    __shared__ int      s_pre[2 * NK];
    __shared__ unsigned s_mask;
    __shared__ int      s_w;

    for (;;) {
        if (tid == 0) s_w = atomicAdd(&g_ticket, 1);
        __syncthreads();
        const int w = s_w;
        if (w >= NTILE) break;

        // tile decode: w = ((t*64 + b)*4 + xb)
        const int xb = w & 3;
        const int b  = (w >> 2) & 63;
        const int t  = w >> 8;
        const int h0 = xb * 16;               // this tile's row base

        const int* __restrict__ pre = (t == 0) ? pre1 : pre2;
        if (tid < 2 * NK) s_pre[tid] = pre[b * 2 * NK + tid];
        __syncthreads();

        // ---- needed-line mask: line L = (row h0+(L>>1), half (L&1)) ----
        if (tid < 32) {
            const int h  = h0 + (tid >> 1);
            const int c0 = (tid & 1) * 32;    // half-row col base
            bool need = false;
#pragma unroll
            for (int k = 0; k < NK; ++k) {
                const int x = s_pre[2 * k + 0];
                const int y = s_pre[2 * k + 1];
                const int left  = max(x - HALFW, 0);
                const int right = min(x + HALFW, MAXC);   // exclusive
                const int down  = max(y - HALFW, 0);
                const int up    = min(y + HALFW, MAXC);   // exclusive
                need |= (h >= left) & (h < right) & (down < c0 + 32) & (up > c0);
            }
            const unsigned m = __ballot_sync(FULLM, need);
            if (tid == 0) s_mask = m;
        }
        __syncthreads();

        const unsigned mask = s_mask;
        const int nlines    = __popc(mask);
        const int j         = tid >> 3;       // line slot 0..31
        const int f         = tid & 7;        // float4 within 128B line

        // ---- channel reduce over needed lines only (proven loop shape) ----
        if (j < nlines) {
            const int line = __fns(mask, 0, j + 1);   // (j+1)-th set bit
            const int lr = line >> 1;
            const int c4 = (line & 1) * 8 + f;        // float4 col 0..15
            const int hw4 = (h0 + lr) * 16 + c4;

            const float4* __restrict__ f4 =
                reinterpret_cast<const float4*>(t == 0 ? f1 : f2);
            const float4* __restrict__ p = f4 + (size_t)b * NC * (HW / 4) + hw4;

            float4 acc = make_float4(0.f, 0.f, 0.f, 0.f);
#pragma unroll 8
            for (int c = 0; c < NC; ++c) {
                float4 v = p[(size_t)c * (HW / 4)];
                acc.x += v.x; acc.y += v.y; acc.z += v.z; acc.w += v.w;
            }
            const float sc = 1.0f / (float)NC;
            float4 o = make_float4(acc.x * sc, acc.y * sc, acc.z * sc, acc.w * sc);
            *reinterpret_cast<float4*>(&s_fm[lr * NW + c4 * 4]) = o;
        }
        __syncthreads();

        // ---- per-tile box partials (x 1/cnt): warp-per-keypoint ----
        for (int k = warp; k < NK; k += 8) {
            const int x = s_pre[2 * k + 0];
            const int y = s_pre[2 * k + 1];
            const int left  = max(x - HALFW, 0);
            const int right = min(x + HALFW, MAXC);
            const int down  = max(y - HALFW, 0);
            const int up    = min(y + HALFW, MAXC);
            const int rl = max(left, h0);
            const int rr = min(right, h0 + 16);
            const int nhl = rr - rl;          // strip-clipped rows, may be <= 0
            const int nw  = up - down;        // 6..12
            const float inv_cnt = 1.0f / (float)((right - left) * nw); // FULL box

            float s = 0.f;
#pragma unroll
            for (int it = 0; it < 5; ++it) {
                const int idx = lane + 32 * it;   // 0..159
                const int r = idx / 12;           // constant divisor -> mul/shift
                const int c = idx - r * 12;
                if ((idx < 144) && (r < nhl) && (c < nw))
                    s += s_fm[(rl - h0 + r) * NW + (down + c)];
            }
#pragma unroll
            for (int off = 16; off > 0; off >>= 1)
                s += __shfl_down_sync(FULLM, s, off);
            if (lane == 0)
                g_part[t][k][xb][b] = s * inv_cnt;    // written exactly once
        }
        __syncthreads();                      // protect s_* before next ticket
    }

    // ---- block exit: all tickets this block will ever draw are drawn ----
    __shared__ int s_last;
    if (lane == 0) __threadfence();           // order this block's g_part stores
    __syncthreads();
    if (tid == 0)
        s_last = (atomicAdd(&g_done, 1) == NBLKP - 1) ? 1 : 0;
    __syncthreads();
    if (!s_last) return;

    // All 444 blocks exited => all 512 tiles processed & stores fenced,
    // and no block will touch g_ticket again => safe to reset counters.
    __threadfence();
    __shared__ float s_fea[2 * NK];
    for (int g = warp; g < 2 * NK; g += 8) {
        const int tt = g / NK;
        const int kk = g - tt * NK;
        float v = 0.f;
#pragma unroll
        for (int xb = 0; xb < 4; ++xb) {
            v += __ldcg(&g_part[tt][kk][xb][lane]);
            v += __ldcg(&g_part[tt][kk][xb][lane + 32]);
        }
#pragma unroll
        for (int off = 16; off > 0; off >>= 1)
            v += __shfl_down_sync(FULLM, v, off);
        if (lane == 0)
            s_fea[g] = v * (1.0f / (float)NB);
    }
    __syncthreads();
    if (tid == 0) {
        float acc2 = 0.f;
#pragma unroll
        for (int kk = 0; kk < NK; ++kk) {
            const float d = s_fea[kk] - 0.999f * s_fea[NK + kk];
            acc2 += d * d;
        }
        out[0] = acc2 * (1.0f / (float)NK);
        g_ticket = 0;                         // reset for next replay
        g_done   = 0;
    }
}

extern "C" void kernel_launch(void* const* d_in, const int* in_sizes, int n_in,
                              void* d_out, int out_size)
{
    const float* f1   = (const float*)d_in[0];
    const float* f2   = (const float*)d_in[1];
    const int*   pre1 = (const int*)d_in[2];
    const int*   pre2 = (const int*)d_in[3];

    fused_kernel<<<NBLKP, 256>>>(f1, f2, pre1, pre2, (float*)d_out);
}

// round 14
// speedup vs baseline: 1.2978x; 1.2978x over previous
#include <cuda_runtime.h>

#define HALFW 6
#define MAXC  63
#define NK    21
#define NB    64
#define NC    256
#define NH    64
#define NW    64
#define HW    (NH * NW)
#define NBLK  512                 // (4, 64, 2)
#define FULLM 0xffffffffu

// Scratch (allocation-free rule: __device__ globals; zero-initialized)
__device__ float g_part[2][NK][4][NB];  // [t][k][xb][b], coalesced finisher
__device__ int   g_done = 0;            // grid completion (self-resetting)

// ---------------------------------------------------------------------------
// Single fused kernel. grid = (4, 64, 2), block = 256.
// Sparse-by-PREDICATION: natural R1 thread->hw4 mapping, each thread tests
// whether its own 128B line intersects any of the 21 boxes and loads only if
// so. No compaction, no ballot, one pre-stream barrier. Box partials and
// coalesced finisher are R12 verbatim (proven 82.0us).
// ---------------------------------------------------------------------------
__global__ void __launch_bounds__(256) fused_kernel(
    const float* __restrict__ f1, const float* __restrict__ f2,
    const int* __restrict__ pre1, const int* __restrict__ pre2,
    float* __restrict__ out)
{
    const int t   = blockIdx.z;
    const int b   = blockIdx.y;
    const int tid = threadIdx.x;
    const int h0  = blockIdx.x * 16;          // this block's row base

    __shared__ __align__(16) float s_fm[16 * NW];  // fm tile (chan-mean), 4KB
    __shared__ int s_pre[2 * NK];

    const int* __restrict__ pre = (t == 0) ? pre1 : pre2;
    if (tid < 2 * NK) s_pre[tid] = pre[b * 2 * NK + tid];
    __syncthreads();

    // ---- per-thread need test for this thread's own 128B line ----
    // natural mapping: tid = lr*16 + half*8 + f  ->  hw4 = h0*16 + tid
    const int lr   = tid >> 4;                // local row 0..15
    const int half = (tid >> 3) & 1;          // 128B half of the row
    {
        const int h  = h0 + lr;
        const int c0 = half * 32;
        bool need = false;
#pragma unroll
        for (int k = 0; k < NK; ++k) {
            const int x = s_pre[2 * k + 0];
            const int y = s_pre[2 * k + 1];
            const int left  = max(x - HALFW, 0);
            const int right = min(x + HALFW, MAXC);   // exclusive
            const int down  = max(y - HALFW, 0);
            const int up    = min(y + HALFW, MAXC);   // exclusive
            need |= (h >= left) & (h < right) & (down < c0 + 32) & (up > c0);
        }

        // ---- channel reduce (proven loop; natural addresses) ----
        if (need) {
            const int hw4 = blockIdx.x * 256 + tid;
            const float4* __restrict__ f4 =
                reinterpret_cast<const float4*>(t == 0 ? f1 : f2);
            const float4* __restrict__ p = f4 + (size_t)b * NC * (HW / 4) + hw4;

            float4 acc = make_float4(0.f, 0.f, 0.f, 0.f);
#pragma unroll 16
            for (int c = 0; c < NC; ++c) {
                float4 v = p[(size_t)c * (HW / 4)];
                acc.x += v.x; acc.y += v.y; acc.z += v.z; acc.w += v.w;
            }
            const float sc = 1.0f / (float)NC;
            float4 o = make_float4(acc.x * sc, acc.y * sc, acc.z * sc, acc.w * sc);
            *reinterpret_cast<float4*>(&s_fm[lr * NW + (tid & 15) * 4]) = o;
        }
    }
    __syncthreads();

    // ---- per-block box partials (x 1/cnt): warp-per-keypoint (R12) ----
    const int warp = tid >> 5;
    const int lane = tid & 31;
    for (int k = warp; k < NK; k += 8) {
        const int x = s_pre[2 * k + 0];
        const int y = s_pre[2 * k + 1];
        const int left  = max(x - HALFW, 0);
        const int right = min(x + HALFW, MAXC);
        const int down  = max(y - HALFW, 0);
        const int up    = min(y + HALFW, MAXC);
        const int rl = max(left, h0);
        const int rr = min(right, h0 + 16);
        const int nhl = rr - rl;              // strip-clipped rows, may be <= 0
        const int nw  = up - down;            // 6..12
        const float inv_cnt = 1.0f / (float)((right - left) * nw);  // FULL box

        float s = 0.f;
#pragma unroll
        for (int it = 0; it < 5; ++it) {
            const int idx = lane + 32 * it;   // 0..159
            const int r = idx / 12;           // constant divisor -> mul/shift
            const int c = idx - r * 12;
            if ((idx < 144) && (r < nhl) && (c < nw))
                s += s_fm[(rl - h0 + r) * NW + (down + c)];
        }
#pragma unroll
        for (int off = 16; off > 0; off >>= 1)
            s += __shfl_down_sync(FULLM, s, off);
        if (lane == 0)
            g_part[t][k][blockIdx.x][b] = s * inv_cnt;  // written every call
    }

    // ---- grid completion: last of 512 blocks finishes (R12) ----
    __shared__ int s_last;
    if (lane == 0) __threadfence();           // order this warp's g_part store
    __syncthreads();
    if (tid == 0)
        s_last = (atomicAdd(&g_done, 1) == NBLK - 1) ? 1 : 0;
    __syncthreads();
    if (!s_last) return;

    __threadfence();
    __shared__ float s_fea[2 * NK];
    // warp per (t,k); lanes read consecutive b -> fully coalesced
    for (int g = warp; g < 2 * NK; g += 8) {
        const int tt = g / NK;
        const int kk = g - tt * NK;
        float v = 0.f;
#pragma unroll
        for (int xb = 0; xb < 4; ++xb) {
            v += __ldcg(&g_part[tt][kk][xb][lane]);
            v += __ldcg(&g_part[tt][kk][xb][lane + 32]);
        }
#pragma unroll
        for (int off = 16; off > 0; off >>= 1)
            v += __shfl_down_sync(FULLM, v, off);
        if (lane == 0)
            s_fea[g] = v * (1.0f / (float)NB);
    }
    __syncthreads();
    if (tid == 0) {
        float acc2 = 0.f;
#pragma unroll
        for (int kk = 0; kk < NK; ++kk) {
            const float d = s_fea[kk] - 0.999f * s_fea[NK + kk];
            acc2 += d * d;
        }
        out[0] = acc2 * (1.0f / (float)NK);
        g_done = 0;                           // reset for next replay
    }
}

extern "C" void kernel_launch(void* const* d_in, const int* in_sizes, int n_in,
                              void* d_out, int out_size)
{
    const float* f1   = (const float*)d_in[0];
    const float* f2   = (const float*)d_in[1];
    const int*   pre1 = (const int*)d_in[2];
    const int*   pre2 = (const int*)d_in[3];

    fused_kernel<<<dim3(4, NB, 2), 256>>>(f1, f2, pre1, pre2, (float*)d_out);
}